// round 8
// baseline (speedup 1.0000x reference)
#include <cuda_runtime.h>

#define HW (768*768)

// XLA algebraic-simplifier semantics: x / const -> x * (1/const)
#define C3  (1.0f / 3.0f)
#define C81 (1.0f / 81.0f)

// ---- packed f32x2 helpers (each lane = independent rn fp32 op) ----
__device__ __forceinline__ unsigned long long addx2(unsigned long long a, unsigned long long b) {
    unsigned long long r; asm("add.rn.f32x2 %0, %1, %2;" : "=l"(r) : "l"(a), "l"(b)); return r;
}
__device__ __forceinline__ unsigned long long mulx2(unsigned long long a, unsigned long long b) {
    unsigned long long r; asm("mul.rn.f32x2 %0, %1, %2;" : "=l"(r) : "l"(a), "l"(b)); return r;
}
// acc - old  ==  fma(old, -1, acc)  (single rounding, == sub.rn per lane)
__device__ __forceinline__ unsigned long long subx2(unsigned long long acc, unsigned long long old) {
    unsigned long long r;
    asm("fma.rn.f32x2 %0, %1, %2, %3;" : "=l"(r)
        : "l"(old), "l"(0xBF800000BF800000ULL), "l"(acc));
    return r;
}
__device__ __forceinline__ unsigned long long pk(float lo, float hi) {
    unsigned long long r; asm("mov.b64 %0, {%1, %2};" : "=l"(r) : "f"(lo), "f"(hi)); return r;
}
__device__ __forceinline__ float flo(unsigned long long v) { return __uint_as_float((unsigned)v); }
__device__ __forceinline__ float fhi(unsigned long long v) { return __uint_as_float((unsigned)(v >> 32)); }

// ---- smem layout (bytes) ----
#define PS_OFF  0            // 40 x 76 float2 (sx,sy), pitch 608B      : 24320
#define PS_PITCH 608
#define M_OFF   24320        // 42 x 80 float mean (dead after phase B) : 13440
#define H2_OFF  24320        // 40 x 64 float2 (hxx,hyy), pitch 512B    : 20480 (overlaps M)
#define H1_OFF  44800        // 20 x 64 float2 (hxy_r, hxy_r+20)        : 10240
#define NQ_OFF  55040        // int flag counter
#define Q_OFF   55044        // flagged-output queue
#define QCAP    512
#define SMEM_BYTES (55044 + QCAP * 4)

// exact-order recompute + eigen + store for one flagged output (i,j local)
__device__ __noinline__ void exact_pixel(const char* Ps, float* ob, int row0, int col0,
                                         int i, int j) {
    float axx = 0.f, ayy = 0.f, axy = 0.f;
    #pragma unroll 1
    for (int r = 0; r < 9; r++) {
        const float2* sp = (const float2*)(Ps + (i + r) * PS_PITCH) + j;
        #pragma unroll
        for (int c = 0; c < 9; c++) {
            float2 s = sp[c];
            axx = __fadd_rn(axx, __fmul_rn(s.x, s.x));
            ayy = __fadd_rn(ayy, __fmul_rn(s.y, s.y));
            axy = __fadd_rn(axy, __fmul_rn(s.x, s.y));
        }
    }
    float xx = __fmul_rn(axx, C81);
    float yy = __fmul_rn(ayy, C81);
    float xy = __fmul_rn(axy, C81);
    float tr = __fadd_rn(xx, yy);
    float bq = -tr;
    float cq = __fsub_rn(__fmul_rn(xx, yy), __fmul_rn(xy, xy));
    float disc = __fsub_rn(__fmul_rn(bq, bq), __fmul_rn(4.f, cq));
    disc = fmaxf(disc, 0.f);
    float deta = __fsqrt_rn(disc);
    float l1 = __fmul_rn(__fadd_rn(tr, deta), 0.5f);
    float yd = __fsub_rn(xx, l1);
    float s2 = __fadd_rn(__fadd_rn(__fmul_rn(xy, xy), __fmul_rn(yd, yd)), 1e-8f);
    float l  = __fadd_rn(__fsqrt_rn(s2), 1e-8f);
    float ex = __fdiv_rn(xy, l);
    float ey = __fdiv_rn(yd, l);
    size_t o = (size_t)(row0 + i) * 768 + (col0 + j);
    ob[o] = ex; ob[o + HW] = ey; ob[o + 2 * HW] = ex;
}

__global__ void __launch_bounds__(256, 4) k_fused(const float* __restrict__ x,
                                                  float* __restrict__ out) {
    extern __shared__ char smem[];
    char*  Ps  = smem + PS_OFF;
    float* M   = (float*)(smem + M_OFF);
    char*  H2  = smem + H2_OFF;
    char*  H1  = smem + H1_OFF;
    int*   nflag = (int*)(smem + NQ_OFF);
    unsigned short* qbuf = (unsigned short*)(smem + Q_OFF);

    const int col0 = blockIdx.x * 64;
    const int row0 = blockIdx.y * 32;
    const int b    = blockIdx.z;
    const int t    = threadIdx.x;
    const float* xb = x + (size_t)b * 3 * HW;
    float* ob = out + (size_t)b * 3 * HW;

    if (t == 0) *nflag = 0;

    // ---- Phase A: M[42][80] = channel mean; M[0][0] <-> src (row0-5, col0-8).
    for (int s = t; s < 42 * 20; s += 256) {
        int mr = s / 20, k = s - mr * 20;
        int gr = row0 - 5 + mr;
        int gc = col0 - 8 + 4 * k;
        float4 v = make_float4(0.f, 0.f, 0.f, 0.f);
        if ((unsigned)gr < 768u && (unsigned)gc <= 764u) {
            size_t off = (size_t)gr * 768 + gc;
            float4 a  = *(const float4*)(xb + off);
            float4 c1 = *(const float4*)(xb + HW + off);
            float4 c2 = *(const float4*)(xb + 2 * HW + off);
            v.x = __fmul_rn(__fadd_rn(__fadd_rn(a.x, c1.x), c2.x), C3);
            v.y = __fmul_rn(__fadd_rn(__fadd_rn(a.y, c1.y), c2.y), C3);
            v.z = __fmul_rn(__fadd_rn(__fadd_rn(a.z, c1.z), c2.z), C3);
            v.w = __fmul_rn(__fadd_rn(__fadd_rn(a.w, c1.w), c2.w), C3);
        }
        *(float4*)&M[mr * 80 + 4 * k] = v;
    }
    __syncthreads();

    // ---- Phase B: Sobel (exact reference op order) -> Ps (sx,sy).
    //      Ps(pr,pc) <-> src (row0-4+pr, col0-4+pc); OOB -> 0.
    for (int s = t; s < 40 * 72; s += 256) {
        int pr = s / 72, pc = s - pr * 72;
        int sr = row0 - 4 + pr, sc = col0 - 4 + pc;
        float sxv = 0.f, syv = 0.f;
        if ((unsigned)sr < 768u && (unsigned)sc < 768u) {
            int mr = pr + 1, mc = pc + 4;
            const float* r0p = &M[(mr - 1) * 80 + mc];
            const float* r1p = &M[ mr      * 80 + mc];
            const float* r2p = &M[(mr + 1) * 80 + mc];
            float m00 = r0p[-1], m01 = r0p[0], m02 = r0p[1];
            float m10 = r1p[-1],               m12 = r1p[1];
            float m20 = r2p[-1], m21 = r2p[0], m22 = r2p[1];

            float rlx_u = __fsub_rn(m02, m00);
            float rlx_c = __fsub_rn(m12, m10);
            float rlx_d = __fsub_rn(m22, m20);
            float tx3 = __fadd_rn(__fadd_rn(rlx_u, rlx_c), rlx_d);
            sxv = __fadd_rn(rlx_c, __fmul_rn(__fmul_rn(tx3, C3), 3.f));

            float btx_l = __fsub_rn(m20, m00);
            float btx_c = __fsub_rn(m21, m01);
            float btx_r = __fsub_rn(m22, m02);
            float ty3 = __fadd_rn(__fadd_rn(btx_l, btx_c), btx_r);
            syv = __fadd_rn(btx_c, __fmul_rn(__fmul_rn(ty3, C3), 3.f));
        }
        *(float2*)(Ps + pr * PS_PITCH + pc * 8) = make_float2(sxv, syv);
    }
    __syncthreads();

    // ---- Phase C1a: horizontal 9-sums of (sx^2, sy^2), packed. 40 rows x 8 segs.
    for (int u = t; u < 320; u += 256) {
        int r = u >> 3, c0 = (u & 7) * 8;
        const char* rowp = Ps + r * PS_PITCH + c0 * 8;
        unsigned long long prod[16];
        #pragma unroll
        for (int k = 0; k < 8; k++) {
            ulonglong2 q = *(const ulonglong2*)(rowp + k * 16);
            prod[2 * k]     = mulx2(q.x, q.x);
            prod[2 * k + 1] = mulx2(q.y, q.y);
        }
        unsigned long long acc = prod[0];
        #pragma unroll
        for (int k = 1; k < 9; k++) acc = addx2(acc, prod[k]);
        char* hp = H2 + r * 512 + c0 * 8;
        *(unsigned long long*)hp = acc;
        #pragma unroll
        for (int i = 1; i < 8; i++) {
            acc = addx2(acc, prod[i + 8]);
            acc = subx2(acc, prod[i - 1]);
            *(unsigned long long*)(hp + i * 8) = acc;
        }
    }
    // ---- Phase C1b: horizontal 9-sums of sx*sy, packed across rows (r, r+20).
    for (int u = t; u < 160; u += 256) {
        int rp = u >> 3, c0 = (u & 7) * 8;
        const char* r0p = Ps + rp * PS_PITCH + c0 * 8;
        const char* r1p = r0p + 20 * PS_PITCH;
        unsigned long long prod[16];
        #pragma unroll
        for (int k = 0; k < 8; k++) {
            float4 a0 = *(const float4*)(r0p + k * 16);
            float4 a1 = *(const float4*)(r1p + k * 16);
            prod[2 * k]     = mulx2(pk(a0.x, a1.x), pk(a0.y, a1.y));
            prod[2 * k + 1] = mulx2(pk(a0.z, a1.z), pk(a0.w, a1.w));
        }
        unsigned long long acc = prod[0];
        #pragma unroll
        for (int k = 1; k < 9; k++) acc = addx2(acc, prod[k]);
        char* hp = H1 + rp * 512 + c0 * 8;
        *(unsigned long long*)hp = acc;
        #pragma unroll
        for (int i = 1; i < 8; i++) {
            acc = addx2(acc, prod[i + 8]);
            acc = subx2(acc, prod[i - 1]);
            *(unsigned long long*)(hp + i * 8) = acc;
        }
    }
    __syncthreads();

    // ---- Phase C2: vertical sliding + eigen; flag near-degenerate pixels.
    {
        const int c  = t & 63;
        const int i0 = (t >> 6) * 8;
        const char* h2 = H2 + c * 8;
        const char* h1 = H1 + c * 8;
        // hxy row r lives at H1 + (r%20)*512 + c*8 + (r<20 ? 0 : 4)
        unsigned long long vacc = *(const unsigned long long*)(h2 + i0 * 512);
        float sacc;
        {
            int r = i0;
            sacc = *(const float*)(h1 + (r < 20 ? r * 512 : (r - 20) * 512 + 4));
        }
        #pragma unroll
        for (int k = 1; k < 9; k++) {
            int r = i0 + k;
            vacc = addx2(vacc, *(const unsigned long long*)(h2 + r * 512));
            sacc = __fadd_rn(sacc, *(const float*)(h1 + (r < 20 ? r * 512 : (r - 20) * 512 + 4)));
        }
        #pragma unroll
        for (int s = 0; s < 8; s++) {
            int i = i0 + s;
            float xx = __fmul_rn(flo(vacc), C81);
            float yy = __fmul_rn(fhi(vacc), C81);
            float xy = __fmul_rn(sacc, C81);
            float tr = __fadd_rn(xx, yy);
            float bq = -tr;
            float cq = __fsub_rn(__fmul_rn(xx, yy), __fmul_rn(xy, xy));
            float disc = __fsub_rn(__fmul_rn(bq, bq), __fmul_rn(4.f, cq));
            disc = fmaxf(disc, 0.f);
            float deta = __fsqrt_rn(disc);
            float l1 = __fmul_rn(__fadd_rn(tr, deta), 0.5f);
            float yd = __fsub_rn(xx, l1);
            float s2r = __fadd_rn(__fmul_rn(xy, xy), __fmul_rn(yd, yd));

            if (s2r < 9e-6f * tr * tr) {
                int qi = atomicAdd(nflag, 1);
                if (qi < QCAP) qbuf[qi] = (unsigned short)((i << 6) | c);
                else exact_pixel(Ps, ob, row0, col0, i, c);
            } else {
                float l  = __fadd_rn(__fsqrt_rn(__fadd_rn(s2r, 1e-8f)), 1e-8f);
                float ex = __fdiv_rn(xy, l);
                float ey = __fdiv_rn(yd, l);
                size_t o = (size_t)(row0 + i) * 768 + (col0 + c);
                ob[o] = ex; ob[o + HW] = ey; ob[o + 2 * HW] = ex;
            }
            if (s < 7) {
                int rn_ = i + 9, ro = i;
                vacc = addx2(vacc, *(const unsigned long long*)(h2 + rn_ * 512));
                vacc = subx2(vacc, *(const unsigned long long*)(h2 + ro * 512));
                float tadd = __fadd_rn(sacc, *(const float*)(h1 + (rn_ < 20 ? rn_ * 512 : (rn_ - 20) * 512 + 4)));
                sacc = __fsub_rn(tadd, *(const float*)(h1 + (ro < 20 ? ro * 512 : (ro - 20) * 512 + 4)));
            }
        }
    }
    __syncthreads();

    // ---- Phase C3: exact recompute of flagged pixels (cooperative, rare).
    int nf = *nflag;
    if (nf > QCAP) nf = QCAP;
    for (int q = t; q < nf; q += 256) {
        int e = qbuf[q];
        exact_pixel(Ps, ob, row0, col0, e >> 6, e & 63);
    }
}

extern "C" void kernel_launch(void* const* d_in, const int* in_sizes, int n_in,
                              void* d_out, int out_size) {
    const float* x = (const float*)d_in[0];
    float* out = (float*)d_out;

    cudaFuncSetAttribute(k_fused, cudaFuncAttributeMaxDynamicSharedMemorySize, SMEM_BYTES);
    dim3 grid(768 / 64, 768 / 32, 32);   // (12, 24, 32)
    k_fused<<<grid, 256, SMEM_BYTES>>>(x, out);
}

// round 9
// speedup vs baseline: 1.0673x; 1.0673x over previous
#include <cuda_runtime.h>

#define HW (768*768)

// XLA algebraic-simplifier semantics: x / const -> x * (1/const)
#define C3  (1.0f / 3.0f)
#define C81 (1.0f / 81.0f)

// ---- packed f32x2 helpers (each lane = independent rn fp32 op) ----
__device__ __forceinline__ unsigned long long addx2(unsigned long long a, unsigned long long b) {
    unsigned long long r; asm("add.rn.f32x2 %0, %1, %2;" : "=l"(r) : "l"(a), "l"(b)); return r;
}
// acc - old == fma(old, -1, acc) (single rounding per lane)
__device__ __forceinline__ unsigned long long subx2(unsigned long long acc, unsigned long long old) {
    unsigned long long r;
    asm("fma.rn.f32x2 %0, %1, %2, %3;" : "=l"(r)
        : "l"(old), "l"(0xBF800000BF800000ULL), "l"(acc));
    return r;
}
__device__ __forceinline__ unsigned long long dup2(float w) {
    unsigned long long r; asm("mov.b64 %0, {%1, %1};" : "=l"(r) : "f"(w)); return r;
}
__device__ __forceinline__ unsigned long long lo0(float w) {   // (w, +0)
    unsigned long long r; asm("mov.b64 %0, {%1, %2};" : "=l"(r) : "f"(w), "f"(0.0f)); return r;
}
__device__ __forceinline__ unsigned long long hi0(float w) {   // (+0, w)
    unsigned long long r; asm("mov.b64 %0, {%1, %2};" : "=l"(r) : "f"(0.0f), "f"(w)); return r;
}
__device__ __forceinline__ float flo(unsigned long long v) { return __uint_as_float((unsigned)v); }
__device__ __forceinline__ float fhi(unsigned long long v) { return __uint_as_float((unsigned)(v >> 32)); }

// column-only swizzle for P2 (bijective; conflict-free per 8-lane phase)
__device__ __forceinline__ unsigned csw(int c) {
    return (unsigned)((c * 8) ^ (c & 16));
}

// ---- smem layout (bytes); P2 pitch 76 float2 = 608 B ----
#define P2_OFF 0                        // 40 x 76 float2 (pxx,pyy)        : 24320
#define P1_OFF 24320                    // 40 x 76 float  (pxy)            : 12160
#define M_OFF  36480                    // 42 x 80 float  (channel mean)   : 13440
#define NQ_OFF 49920
#define Q_OFF  49924
#define QCAP   512
#define SMEM_BYTES (49924 + QCAP * 2)

// exact-order recompute (reduce_window flat row-major on stored products)
// + strict-rn eigen chain + store, for one flagged output (i,j local)
__device__ __noinline__ void exact_pixel(const char* P2b, const float* P1, float* ob,
                                         int row0, int col0, int i, int j) {
    float axx = 0.f, ayy = 0.f, axy = 0.f;
    #pragma unroll 1
    for (int r = 0; r < 9; r++) {
        const char*  p2r = P2b + (i + r) * 608;
        const float* p1r = P1 + (i + r) * 76;
        #pragma unroll
        for (int c = 0; c < 9; c++) {
            float2 p = *(const float2*)(p2r + csw(j + c));
            axx = __fadd_rn(axx, p.x);
            ayy = __fadd_rn(ayy, p.y);
            axy = __fadd_rn(axy, p1r[j + c]);
        }
    }
    float xx = __fmul_rn(axx, C81);
    float yy = __fmul_rn(ayy, C81);
    float xy = __fmul_rn(axy, C81);
    float tr = __fadd_rn(xx, yy);
    float bq = -tr;
    float cq = __fsub_rn(__fmul_rn(xx, yy), __fmul_rn(xy, xy));
    float disc = __fsub_rn(__fmul_rn(bq, bq), __fmul_rn(4.f, cq));
    disc = fmaxf(disc, 0.f);
    float deta = __fsqrt_rn(disc);
    float l1 = __fmul_rn(__fadd_rn(tr, deta), 0.5f);
    float yd = __fsub_rn(xx, l1);
    float s2 = __fadd_rn(__fadd_rn(__fmul_rn(xy, xy), __fmul_rn(yd, yd)), 1e-8f);
    float l  = __fadd_rn(__fsqrt_rn(s2), 1e-8f);
    float ex = __fdiv_rn(xy, l);
    float ey = __fdiv_rn(yd, l);
    size_t o = (size_t)(row0 + i) * 768 + (col0 + j);
    ob[o] = ex; ob[o + HW] = ey; ob[o + 2 * HW] = ex;
}

// one product row: horizontal 9-sums in registers (order-free fast path),
// vertical accumulate. MODE 0: first row (out row 0 only); 1: middle (both);
// 2: last (out row 1 only). xy packed across the two output rows.
template<int MODE>
__device__ __forceinline__ void row_sep(
    const char* __restrict__ P2b, const float4* __restrict__ P1v,
    unsigned (&ap2)[6], int& ip1,
    unsigned long long (&a2)[2][4], unsigned long long (&axy2)[4])
{
    unsigned long long w2[12];
    #pragma unroll
    for (int k = 0; k < 6; k++) {
        ulonglong2 q = *(const ulonglong2*)(P2b + ap2[k]);
        w2[2 * k] = q.x; w2[2 * k + 1] = q.y;
        ap2[k] += 608;
    }
    float w1[12];
    float4 f0 = P1v[ip1], f1 = P1v[ip1 + 1], f2 = P1v[ip1 + 2];
    ip1 += 19;
    w1[0] = f0.x; w1[1] = f0.y; w1[2]  = f0.z; w1[3]  = f0.w;
    w1[4] = f1.x; w1[5] = f1.y; w1[6]  = f1.z; w1[7]  = f1.w;
    w1[8] = f2.x; w1[9] = f2.y; w1[10] = f2.z; w1[11] = f2.w;

    // horizontal 9-sums of packed (pxx,pyy): tree init + 3 slides
    unsigned long long h[4];
    {
        unsigned long long t01 = addx2(w2[0], w2[1]), t23 = addx2(w2[2], w2[3]);
        unsigned long long t45 = addx2(w2[4], w2[5]), t67 = addx2(w2[6], w2[7]);
        h[0] = addx2(addx2(addx2(t01, t23), addx2(t45, t67)), w2[8]);
        h[1] = subx2(addx2(h[0], w2[9]),  w2[0]);
        h[2] = subx2(addx2(h[1], w2[10]), w2[1]);
        h[3] = subx2(addx2(h[2], w2[11]), w2[2]);
    }
    // horizontal 9-sums of pxy (scalar): tree init + 3 slides
    float s[4];
    {
        float t01 = __fadd_rn(w1[0], w1[1]), t23 = __fadd_rn(w1[2], w1[3]);
        float t45 = __fadd_rn(w1[4], w1[5]), t67 = __fadd_rn(w1[6], w1[7]);
        s[0] = __fadd_rn(__fadd_rn(__fadd_rn(t01, t23), __fadd_rn(t45, t67)), w1[8]);
        s[1] = __fsub_rn(__fadd_rn(s[0], w1[9]),  w1[0]);
        s[2] = __fsub_rn(__fadd_rn(s[1], w1[10]), w1[1]);
        s[3] = __fsub_rn(__fadd_rn(s[2], w1[11]), w1[2]);
    }
    #pragma unroll
    for (int cc = 0; cc < 4; cc++) {
        if (MODE != 2) a2[0][cc] = addx2(a2[0][cc], h[cc]);
        if (MODE != 0) a2[1][cc] = addx2(a2[1][cc], h[cc]);
        unsigned long long wd = (MODE == 0) ? lo0(s[cc])
                              : (MODE == 2) ? hi0(s[cc])
                                            : dup2(s[cc]);
        axy2[cc] = addx2(axy2[cc], wd);
    }
}

__global__ void __launch_bounds__(256, 4) k_fused(const float* __restrict__ x,
                                                  float* __restrict__ out) {
    extern __shared__ char smem[];
    char*  P2b = smem + P2_OFF;
    float* P1  = (float*)(smem + P1_OFF);
    float* M   = (float*)(smem + M_OFF);
    int*   nflag = (int*)(smem + NQ_OFF);
    unsigned short* qbuf = (unsigned short*)(smem + Q_OFF);

    const int col0 = blockIdx.x * 64;
    const int row0 = blockIdx.y * 32;
    const int b    = blockIdx.z;
    const int t    = threadIdx.x;
    const float* xb = x + (size_t)b * 3 * HW;
    float* ob = out + (size_t)b * 3 * HW;

    if (t == 0) *nflag = 0;

    // ---- Phase A: M[42][80] = channel mean; M[0][0] <-> src (row0-5, col0-8).
    for (int s = t; s < 42 * 20; s += 256) {
        int mr = s / 20, k = s - mr * 20;
        int gr = row0 - 5 + mr;
        int gc = col0 - 8 + 4 * k;
        float4 v = make_float4(0.f, 0.f, 0.f, 0.f);
        if ((unsigned)gr < 768u && (unsigned)gc <= 764u) {
            size_t off = (size_t)gr * 768 + gc;
            float4 a  = *(const float4*)(xb + off);
            float4 c1 = *(const float4*)(xb + HW + off);
            float4 c2 = *(const float4*)(xb + 2 * HW + off);
            v.x = __fmul_rn(__fadd_rn(__fadd_rn(a.x, c1.x), c2.x), C3);
            v.y = __fmul_rn(__fadd_rn(__fadd_rn(a.y, c1.y), c2.y), C3);
            v.z = __fmul_rn(__fadd_rn(__fadd_rn(a.z, c1.z), c2.z), C3);
            v.w = __fmul_rn(__fadd_rn(__fadd_rn(a.w, c1.w), c2.w), C3);
        }
        *(float4*)&M[mr * 80 + 4 * k] = v;
    }
    __syncthreads();

    // ---- Phase B: Sobel (exact reference op order) + products into P2/P1.
    for (int s = t; s < 40 * 72; s += 256) {
        int pr = s / 72, pc = s - pr * 72;
        int sr = row0 - 4 + pr, sc = col0 - 4 + pc;
        float pxx = 0.f, pyy = 0.f, pxy = 0.f;
        if ((unsigned)sr < 768u && (unsigned)sc < 768u) {
            int mr = pr + 1, mc = pc + 4;
            const float* r0p = &M[(mr - 1) * 80 + mc];
            const float* r1p = &M[ mr      * 80 + mc];
            const float* r2p = &M[(mr + 1) * 80 + mc];
            float m00 = r0p[-1], m01 = r0p[0], m02 = r0p[1];
            float m10 = r1p[-1],               m12 = r1p[1];
            float m20 = r2p[-1], m21 = r2p[0], m22 = r2p[1];

            float rlx_u = __fsub_rn(m02, m00);
            float rlx_c = __fsub_rn(m12, m10);
            float rlx_d = __fsub_rn(m22, m20);
            float tx3 = __fadd_rn(__fadd_rn(rlx_u, rlx_c), rlx_d);
            float sxv = __fadd_rn(rlx_c, __fmul_rn(__fmul_rn(tx3, C3), 3.f));

            float btx_l = __fsub_rn(m20, m00);
            float btx_c = __fsub_rn(m21, m01);
            float btx_r = __fsub_rn(m22, m02);
            float ty3 = __fadd_rn(__fadd_rn(btx_l, btx_c), btx_r);
            float syv = __fadd_rn(btx_c, __fmul_rn(__fmul_rn(ty3, C3), 3.f));

            pxx = __fmul_rn(sxv, sxv);
            pyy = __fmul_rn(syv, syv);
            pxy = __fmul_rn(sxv, syv);
        }
        *(float2*)(P2b + pr * 608 + csw(pc)) = make_float2(pxx, pyy);
        P1[pr * 76 + pc] = pxy;
    }
    __syncthreads();

    // ---- Phase C: 2 rows x 4 cols per thread; separable in-register sums.
    const int uj = t & 15, ui = t >> 4;
    const int oc   = uj * 4;
    const int orow = ui * 2;

    unsigned long long a2[2][4];
    unsigned long long axy2[4];
    #pragma unroll
    for (int cc = 0; cc < 4; cc++) { a2[0][cc] = 0ull; a2[1][cc] = 0ull; axy2[cc] = 0ull; }

    unsigned ap2[6];
    #pragma unroll
    for (int k = 0; k < 6; k++) ap2[k] = (unsigned)(orow * 608) + csw(oc + 2 * k);
    const float4* P1v = (const float4*)P1;
    int ip1 = orow * 19 + uj;

    row_sep<0>(P2b, P1v, ap2, ip1, a2, axy2);
    row_sep<1>(P2b, P1v, ap2, ip1, a2, axy2);
    row_sep<1>(P2b, P1v, ap2, ip1, a2, axy2);
    row_sep<1>(P2b, P1v, ap2, ip1, a2, axy2);
    row_sep<1>(P2b, P1v, ap2, ip1, a2, axy2);
    row_sep<1>(P2b, P1v, ap2, ip1, a2, axy2);
    row_sep<1>(P2b, P1v, ap2, ip1, a2, axy2);
    row_sep<1>(P2b, P1v, ap2, ip1, a2, axy2);
    row_sep<1>(P2b, P1v, ap2, ip1, a2, axy2);
    row_sep<2>(P2b, P1v, ap2, ip1, a2, axy2);

    // ---- eigen math + flag + vectorized store
    #pragma unroll
    for (int oi = 0; oi < 2; oi++) {
        float ex4[4], ey4[4];
        #pragma unroll
        for (int cc = 0; cc < 4; cc++) {
            unsigned long long v = a2[oi][cc];
            float xx = __fmul_rn(flo(v), C81);
            float yy = __fmul_rn(fhi(v), C81);
            unsigned long long vq = axy2[cc];
            float xy = __fmul_rn(oi == 0 ? flo(vq) : fhi(vq), C81);
            float tr = __fadd_rn(xx, yy);
            float bq = -tr;
            float cq = __fsub_rn(__fmul_rn(xx, yy), __fmul_rn(xy, xy));
            float disc = __fsub_rn(__fmul_rn(bq, bq), __fmul_rn(4.f, cq));
            disc = fmaxf(disc, 0.f);
            float deta = __fsqrt_rn(disc);
            float l1 = __fmul_rn(__fadd_rn(tr, deta), 0.5f);
            float yd = __fsub_rn(xx, l1);
            float s2r = __fadd_rn(__fmul_rn(xy, xy), __fmul_rn(yd, yd));

            if (s2r < 9e-6f * tr * tr) {   // near-degenerate: queue exact recompute
                int qi = atomicAdd(nflag, 1);
                int li = orow + oi, lj = oc + cc;
                if (qi < QCAP) qbuf[qi] = (unsigned short)((li << 6) | lj);
                else exact_pixel(P2b, P1, ob, row0, col0, li, lj);
            }
            float l  = __fadd_rn(__fsqrt_rn(__fadd_rn(s2r, 1e-8f)), 1e-8f);
            ex4[cc] = __fdiv_rn(xy, l);
            ey4[cc] = __fdiv_rn(yd, l);
        }
        size_t o = (size_t)(row0 + orow + oi) * 768 + (col0 + oc);
        *(float4*)&ob[o]          = make_float4(ex4[0], ex4[1], ex4[2], ex4[3]);
        *(float4*)&ob[o + HW]     = make_float4(ey4[0], ey4[1], ey4[2], ey4[3]);
        *(float4*)&ob[o + 2*HW]   = make_float4(ex4[0], ex4[1], ex4[2], ex4[3]);
    }
    __syncthreads();

    // ---- Phase D: exact overwrite of flagged pixels (rare; single writer each).
    int nf = *nflag;
    if (nf > QCAP) nf = QCAP;
    for (int q = t; q < nf; q += 256) {
        int e = qbuf[q];
        exact_pixel(P2b, P1, ob, row0, col0, e >> 6, e & 63);
    }
}

extern "C" void kernel_launch(void* const* d_in, const int* in_sizes, int n_in,
                              void* d_out, int out_size) {
    const float* x = (const float*)d_in[0];
    float* out = (float*)d_out;

    cudaFuncSetAttribute(k_fused, cudaFuncAttributeMaxDynamicSharedMemorySize, SMEM_BYTES);
    dim3 grid(768 / 64, 768 / 32, 32);   // (12, 24, 32)
    k_fused<<<grid, 256, SMEM_BYTES>>>(x, out);
}

// round 10
// speedup vs baseline: 1.3509x; 1.2657x over previous
#include <cuda_runtime.h>

#define HW (768*768)

// XLA algebraic-simplifier semantics: x / const -> x * (1/const)
#define C3  (1.0f / 3.0f)
#define C81 (1.0f / 81.0f)

// ---- packed f32x2 helpers (each lane = independent rn fp32 op) ----
__device__ __forceinline__ unsigned long long addx2(unsigned long long a, unsigned long long b) {
    unsigned long long r; asm("add.rn.f32x2 %0, %1, %2;" : "=l"(r) : "l"(a), "l"(b)); return r;
}
__device__ __forceinline__ unsigned long long mulx2(unsigned long long a, unsigned long long b) {
    unsigned long long r; asm("mul.rn.f32x2 %0, %1, %2;" : "=l"(r) : "l"(a), "l"(b)); return r;
}
// acc - old == fma(old, -1, acc) (single rounding per lane)
__device__ __forceinline__ unsigned long long subx2(unsigned long long acc, unsigned long long old) {
    unsigned long long r;
    asm("fma.rn.f32x2 %0, %1, %2, %3;" : "=l"(r)
        : "l"(old), "l"(0xBF800000BF800000ULL), "l"(acc));
    return r;
}
__device__ __forceinline__ float flo(unsigned long long v) { return __uint_as_float((unsigned)v); }
__device__ __forceinline__ float fhi(unsigned long long v) { return __uint_as_float((unsigned)(v >> 32)); }

// column-only swizzle (bijective; conflict-free per 8-lane phase; row pitch 608B keeps bit4 clear)
__device__ __forceinline__ unsigned csw(int c) {
    return (unsigned)((c * 8) ^ (c & 16));
}

// ---- smem layout (bytes) ----
// Ps : 56 rows x 76 float2 (sx,sy), pitch 608   : 34048
// M  : 58 rows x 80 float (channel mean)        : 18560
#define PS_OFF 0
#define M_OFF  34048
#define NQ_OFF 52608
#define Q_OFF  52612
#define QCAP   512
#define SMEM_BYTES (52612 + QCAP * 2)

// exact-order recompute (reduce_window flat row-major, products on the fly)
// + strict-rn eigen chain + store, for one flagged output (i,j local)
__device__ __noinline__ void exact_pixel(const char* Ps, float* ob,
                                         int row0, int col0, int i, int j) {
    float axx = 0.f, ayy = 0.f, axy = 0.f;
    #pragma unroll 1
    for (int r = 0; r < 9; r++) {
        const char* pr = Ps + (i + r) * 608;
        #pragma unroll
        for (int c = 0; c < 9; c++) {
            float2 s = *(const float2*)(pr + csw(j + c));
            axx = __fadd_rn(axx, __fmul_rn(s.x, s.x));
            ayy = __fadd_rn(ayy, __fmul_rn(s.y, s.y));
            axy = __fadd_rn(axy, __fmul_rn(s.x, s.y));
        }
    }
    float xx = __fmul_rn(axx, C81);
    float yy = __fmul_rn(ayy, C81);
    float xy = __fmul_rn(axy, C81);
    float tr = __fadd_rn(xx, yy);
    float bq = -tr;
    float cq = __fsub_rn(__fmul_rn(xx, yy), __fmul_rn(xy, xy));
    float disc = __fsub_rn(__fmul_rn(bq, bq), __fmul_rn(4.f, cq));
    disc = fmaxf(disc, 0.f);
    float deta = __fsqrt_rn(disc);
    float l1 = __fmul_rn(__fadd_rn(tr, deta), 0.5f);
    float yd = __fsub_rn(xx, l1);
    float s2 = __fadd_rn(__fadd_rn(__fmul_rn(xy, xy), __fmul_rn(yd, yd)), 1e-8f);
    float l  = __fadd_rn(__fsqrt_rn(s2), 1e-8f);
    float ex = __fdiv_rn(xy, l);
    float ey = __fdiv_rn(yd, l);
    size_t o = (size_t)(row0 + i) * 768 + (col0 + j);
    ob[o] = ex; ob[o + HW] = ey; ob[o + 2 * HW] = ex;
}

// one (sx,sy) row: products on the fly, horizontal 9-sums in registers
// (tree + 3 slides, order-free fast path), vertical accumulate into output
// rows [LO..HI] of this thread's 3-row block.
template<int LO, int HI>
__device__ __forceinline__ void row3(
    const char* __restrict__ Ps, unsigned (&ap2)[6],
    unsigned long long (&a2)[3][4], float (&axy)[3][4])
{
    // chunk 0,1: q0..q3 -> keep p0,p1,p2 (and s0,s1,s2) for the slides
    ulonglong2 A = *(const ulonglong2*)(Ps + ap2[0]);  ap2[0] += 608;
    ulonglong2 B = *(const ulonglong2*)(Ps + ap2[1]);  ap2[1] += 608;
    unsigned long long p0 = mulx2(A.x, A.x), p1 = mulx2(A.y, A.y);
    unsigned long long p2 = mulx2(B.x, B.x), p3 = mulx2(B.y, B.y);
    float s0 = __fmul_rn(flo(A.x), fhi(A.x));
    float s1 = __fmul_rn(flo(A.y), fhi(A.y));
    float s2v = __fmul_rn(flo(B.x), fhi(B.x));
    float s3 = __fmul_rn(flo(B.y), fhi(B.y));
    unsigned long long t  = addx2(addx2(p0, p1), addx2(p2, p3));
    float ts = __fadd_rn(__fadd_rn(s0, s1), __fadd_rn(s2v, s3));

    // chunk 2,3: q4..q7 (nothing kept)
    A = *(const ulonglong2*)(Ps + ap2[2]);  ap2[2] += 608;
    B = *(const ulonglong2*)(Ps + ap2[3]);  ap2[3] += 608;
    {
        unsigned long long p4 = mulx2(A.x, A.x), p5 = mulx2(A.y, A.y);
        unsigned long long p6 = mulx2(B.x, B.x), p7 = mulx2(B.y, B.y);
        t  = addx2(t, addx2(addx2(p4, p5), addx2(p6, p7)));
        float u0 = __fmul_rn(flo(A.x), fhi(A.x));
        float u1 = __fmul_rn(flo(A.y), fhi(A.y));
        float u2 = __fmul_rn(flo(B.x), fhi(B.x));
        float u3 = __fmul_rn(flo(B.y), fhi(B.y));
        ts = __fadd_rn(ts, __fadd_rn(__fadd_rn(u0, u1), __fadd_rn(u2, u3)));
    }

    // chunk 4,5: q8..q11 -> finish h0..h3 / s-sums
    A = *(const ulonglong2*)(Ps + ap2[4]);  ap2[4] += 608;
    B = *(const ulonglong2*)(Ps + ap2[5]);  ap2[5] += 608;
    unsigned long long h0, h1, h2, h3;
    float w0, w1, w2, w3;
    {
        unsigned long long p8 = mulx2(A.x, A.x), p9 = mulx2(A.y, A.y);
        unsigned long long p10 = mulx2(B.x, B.x), p11 = mulx2(B.y, B.y);
        h0 = addx2(t, p8);
        h1 = subx2(addx2(h0, p9),  p0);
        h2 = subx2(addx2(h1, p10), p1);
        h3 = subx2(addx2(h2, p11), p2);
        float u8 = __fmul_rn(flo(A.x), fhi(A.x));
        float u9 = __fmul_rn(flo(A.y), fhi(A.y));
        float u10 = __fmul_rn(flo(B.x), fhi(B.x));
        float u11 = __fmul_rn(flo(B.y), fhi(B.y));
        w0 = __fadd_rn(ts, u8);
        w1 = __fsub_rn(__fadd_rn(w0, u9),  s0);
        w2 = __fsub_rn(__fadd_rn(w1, u10), s1);
        w3 = __fsub_rn(__fadd_rn(w2, u11), s2v);
    }

    #pragma unroll
    for (int oi = LO; oi <= HI; oi++) {
        a2[oi][0] = addx2(a2[oi][0], h0);
        a2[oi][1] = addx2(a2[oi][1], h1);
        a2[oi][2] = addx2(a2[oi][2], h2);
        a2[oi][3] = addx2(a2[oi][3], h3);
        axy[oi][0] = __fadd_rn(axy[oi][0], w0);
        axy[oi][1] = __fadd_rn(axy[oi][1], w1);
        axy[oi][2] = __fadd_rn(axy[oi][2], w2);
        axy[oi][3] = __fadd_rn(axy[oi][3], w3);
    }
}

__global__ void __launch_bounds__(256, 3) k_fused(const float* __restrict__ x,
                                                  float* __restrict__ out) {
    extern __shared__ char smem[];
    char*  Ps  = smem + PS_OFF;
    float* M   = (float*)(smem + M_OFF);
    int*   nflag = (int*)(smem + NQ_OFF);
    unsigned short* qbuf = (unsigned short*)(smem + Q_OFF);

    const int col0 = blockIdx.x * 64;
    const int row0 = blockIdx.y * 48;
    const int b    = blockIdx.z;
    const int t    = threadIdx.x;
    const float* xb = x + (size_t)b * 3 * HW;
    float* ob = out + (size_t)b * 3 * HW;

    if (t == 0) *nflag = 0;

    // ---- Phase A: M[58][80] = channel mean; M[0][0] <-> src (row0-5, col0-8).
    for (int s = t; s < 58 * 20; s += 256) {
        int mr = s / 20, k = s - mr * 20;
        int gr = row0 - 5 + mr;
        int gc = col0 - 8 + 4 * k;
        float4 v = make_float4(0.f, 0.f, 0.f, 0.f);
        if ((unsigned)gr < 768u && (unsigned)gc <= 764u) {
            size_t off = (size_t)gr * 768 + gc;
            float4 a  = *(const float4*)(xb + off);
            float4 c1 = *(const float4*)(xb + HW + off);
            float4 c2 = *(const float4*)(xb + 2 * HW + off);
            v.x = __fmul_rn(__fadd_rn(__fadd_rn(a.x, c1.x), c2.x), C3);
            v.y = __fmul_rn(__fadd_rn(__fadd_rn(a.y, c1.y), c2.y), C3);
            v.z = __fmul_rn(__fadd_rn(__fadd_rn(a.z, c1.z), c2.z), C3);
            v.w = __fmul_rn(__fadd_rn(__fadd_rn(a.w, c1.w), c2.w), C3);
        }
        *(float4*)&M[mr * 80 + 4 * k] = v;
    }
    __syncthreads();

    // ---- Phase B: Sobel (exact reference op order) -> Ps (sx,sy), swizzled.
    //      Ps(pr,pc) <-> src (row0-4+pr, col0-4+pc); OOB -> 0.
    for (int s = t; s < 56 * 72; s += 256) {
        int pr = s / 72, pc = s - pr * 72;
        int sr = row0 - 4 + pr, sc = col0 - 4 + pc;
        float sxv = 0.f, syv = 0.f;
        if ((unsigned)sr < 768u && (unsigned)sc < 768u) {
            int mr = pr + 1, mc = pc + 4;
            const float* r0p = &M[(mr - 1) * 80 + mc];
            const float* r1p = &M[ mr      * 80 + mc];
            const float* r2p = &M[(mr + 1) * 80 + mc];
            float m00 = r0p[-1], m01 = r0p[0], m02 = r0p[1];
            float m10 = r1p[-1],               m12 = r1p[1];
            float m20 = r2p[-1], m21 = r2p[0], m22 = r2p[1];

            float rlx_u = __fsub_rn(m02, m00);
            float rlx_c = __fsub_rn(m12, m10);
            float rlx_d = __fsub_rn(m22, m20);
            float tx3 = __fadd_rn(__fadd_rn(rlx_u, rlx_c), rlx_d);
            sxv = __fadd_rn(rlx_c, __fmul_rn(__fmul_rn(tx3, C3), 3.f));

            float btx_l = __fsub_rn(m20, m00);
            float btx_c = __fsub_rn(m21, m01);
            float btx_r = __fsub_rn(m22, m02);
            float ty3 = __fadd_rn(__fadd_rn(btx_l, btx_c), btx_r);
            syv = __fadd_rn(btx_c, __fmul_rn(__fmul_rn(ty3, C3), 3.f));
        }
        *(float2*)(Ps + pr * 608 + csw(pc)) = make_float2(sxv, syv);
    }
    __syncthreads();

    // ---- Phase C: 3 rows x 4 cols per thread; 11-row sweep, carried addresses.
    const int uj = t & 15, ui = t >> 4;     // 16 col-groups x 16 row-groups
    const int oc   = uj * 4;
    const int orow = ui * 3;

    unsigned long long a2[3][4];
    float axy[3][4];
    #pragma unroll
    for (int oi = 0; oi < 3; oi++)
        #pragma unroll
        for (int cc = 0; cc < 4; cc++) { a2[oi][cc] = 0ull; axy[oi][cc] = 0.f; }

    unsigned ap2[6];
    #pragma unroll
    for (int k = 0; k < 6; k++) ap2[k] = (unsigned)(orow * 608) + csw(oc + 2 * k);

    row3<0, 0>(Ps, ap2, a2, axy);
    row3<0, 1>(Ps, ap2, a2, axy);
    row3<0, 2>(Ps, ap2, a2, axy);
    row3<0, 2>(Ps, ap2, a2, axy);
    row3<0, 2>(Ps, ap2, a2, axy);
    row3<0, 2>(Ps, ap2, a2, axy);
    row3<0, 2>(Ps, ap2, a2, axy);
    row3<0, 2>(Ps, ap2, a2, axy);
    row3<0, 2>(Ps, ap2, a2, axy);
    row3<1, 2>(Ps, ap2, a2, axy);
    row3<2, 2>(Ps, ap2, a2, axy);

    // ---- eigen math + flag + vectorized store
    #pragma unroll
    for (int oi = 0; oi < 3; oi++) {
        float ex4[4], ey4[4];
        #pragma unroll
        for (int cc = 0; cc < 4; cc++) {
            unsigned long long v = a2[oi][cc];
            float xx = __fmul_rn(flo(v), C81);
            float yy = __fmul_rn(fhi(v), C81);
            float xy = __fmul_rn(axy[oi][cc], C81);
            float tr = __fadd_rn(xx, yy);
            float bq = -tr;
            float cq = __fsub_rn(__fmul_rn(xx, yy), __fmul_rn(xy, xy));
            float disc = __fsub_rn(__fmul_rn(bq, bq), __fmul_rn(4.f, cq));
            disc = fmaxf(disc, 0.f);
            float deta = __fsqrt_rn(disc);
            float l1 = __fmul_rn(__fadd_rn(tr, deta), 0.5f);
            float yd = __fsub_rn(xx, l1);
            float s2r = __fadd_rn(__fmul_rn(xy, xy), __fmul_rn(yd, yd));

            if (s2r < 9e-6f * tr * tr) {   // near-degenerate: queue exact recompute
                int qi = atomicAdd(nflag, 1);
                int li = orow + oi, lj = oc + cc;
                if (qi < QCAP) qbuf[qi] = (unsigned short)((li << 6) | lj);
                else exact_pixel(Ps, ob, row0, col0, li, lj);
            }
            float l  = __fadd_rn(__fsqrt_rn(__fadd_rn(s2r, 1e-8f)), 1e-8f);
            ex4[cc] = __fdiv_rn(xy, l);
            ey4[cc] = __fdiv_rn(yd, l);
        }
        size_t o = (size_t)(row0 + orow + oi) * 768 + (col0 + oc);
        *(float4*)&ob[o]          = make_float4(ex4[0], ex4[1], ex4[2], ex4[3]);
        *(float4*)&ob[o + HW]     = make_float4(ey4[0], ey4[1], ey4[2], ey4[3]);
        *(float4*)&ob[o + 2*HW]   = make_float4(ex4[0], ex4[1], ex4[2], ex4[3]);
    }
    __syncthreads();

    // ---- Phase D: exact overwrite of flagged pixels (rare; single writer each).
    int nf = *nflag;
    if (nf > QCAP) nf = QCAP;
    for (int q = t; q < nf; q += 256) {
        int e = qbuf[q];
        exact_pixel(Ps, ob, row0, col0, e >> 6, e & 63);
    }
}

extern "C" void kernel_launch(void* const* d_in, const int* in_sizes, int n_in,
                              void* d_out, int out_size) {
    const float* x = (const float*)d_in[0];
    float* out = (float*)d_out;

    cudaFuncSetAttribute(k_fused, cudaFuncAttributeMaxDynamicSharedMemorySize, SMEM_BYTES);
    dim3 grid(768 / 64, 768 / 48, 32);   // (12, 16, 32)
    k_fused<<<grid, 256, SMEM_BYTES>>>(x, out);
}